// round 12
// baseline (speedup 1.0000x reference)
#include <cuda_runtime.h>

#define NQ   2048
#define NS   320
#define DIM  256
#define NWAY 20

typedef unsigned long long u64;

__device__ float g_qproj[NQ * DIM];
__device__ float g_sproj[NS * DIM];

// ---- packed f32x2 helpers ----
__device__ __forceinline__ u64 add2(u64 a, u64 b) {
    u64 d; asm("add.rn.f32x2 %0, %1, %2;" : "=l"(d) : "l"(a), "l"(b)); return d;
}
__device__ __forceinline__ u64 fma2(u64 a, u64 b, u64 c) {
    u64 d; asm("fma.rn.f32x2 %0, %1, %2, %3;" : "=l"(d) : "l"(a), "l"(b), "l"(c)); return d;
}
__device__ __forceinline__ u64 dup2(float x) {
    u64 r; unsigned xi = __float_as_uint(x);
    asm("mov.b64 %0, {%1, %1};" : "=l"(r) : "r"(xi)); return r;
}
__device__ __forceinline__ float lo2(u64 v) { return __uint_as_float((unsigned)v); }
__device__ __forceinline__ float hi2(u64 v) { return __uint_as_float((unsigned)(v >> 32)); }

__device__ __forceinline__ void cpa16(void* dst, const void* src) {
    unsigned sa = (unsigned)__cvta_generic_to_shared(dst);
    asm volatile("cp.async.cg.shared.global [%0], [%1], 16;" :: "r"(sa), "l"(src));
}

// ---------------------------------------------------------------------------
// Kernel A: projections — R6 version verbatim (measured 16.1us)
// ---------------------------------------------------------------------------
#define PBK   64
#define PADA  65
#define PADB  68
#define ASTG  (PBK * PADA)
#define BSTG  (PBK * PADB)

__global__ void __launch_bounds__(256) proj_kernel(
    const float* __restrict__ support, const float* __restrict__ query,
    const float* __restrict__ W1, const float* __restrict__ b1)
{
    extern __shared__ __align__(16) unsigned char psm[];
    u64*   AsD = (u64*)psm;
    float* Bs  = (float*)(AsD + 2 * ASTG);

    const int tile_n = blockIdx.x;
    const int tile_m = blockIdx.y;
    const bool is_sup = (tile_m >= NQ / 64);

    const float* Amat;
    const float* Bmat;
    int m0;
    if (is_sup) { m0 = (tile_m - NQ / 64) * 64; Amat = support; Bmat = W1 + DIM * DIM; }
    else        { m0 = tile_m * 64;             Amat = query;   Bmat = W1; }
    const int n0 = tile_n * 64;

    const int tid = threadIdx.x;
    const int tx = tid & 15;
    const int ty = tid >> 4;

    const int t_m = tid >> 2;
    const int t_k = (tid & 3) * 4;

    const int b_row = tid >> 2;
    const int b_q   = tid & 3;

    const float* Arow = Amat + (m0 + t_m) * DIM;
    const float* Brow = Bmat + b_row * DIM + n0;

    u64 acc[4][2];
    #pragma unroll
    for (int i = 0; i < 4; i++) { acc[i][0] = 0ull; acc[i][1] = 0ull; }

    float4 areg[4];

    #pragma unroll
    for (int u = 0; u < 4; u++)
        areg[u] = *(const float4*)(Arow + t_k + u * 16);
    #pragma unroll
    for (int u = 0; u < 4; u++) {
        const int kk = t_k + u * 16;
        AsD[(kk + 0) * PADA + t_m] = dup2(areg[u].x);
        AsD[(kk + 1) * PADA + t_m] = dup2(areg[u].y);
        AsD[(kk + 2) * PADA + t_m] = dup2(areg[u].z);
        AsD[(kk + 3) * PADA + t_m] = dup2(areg[u].w);
    }
    #pragma unroll
    for (int u = 0; u < 4; u++) {
        const int c4 = b_q + u * 4;
        cpa16(&Bs[b_row * PADB + c4 * 4], Brow + c4 * 4);
    }
    asm volatile("cp.async.commit_group;");

    #pragma unroll
    for (int s = 0; s < 4; s++) {
        const int buf = s & 1;
        asm volatile("cp.async.wait_group 0;");
        __syncthreads();

        if (s < 3) {
            const int k0n = (s + 1) * PBK;
            #pragma unroll
            for (int u = 0; u < 4; u++)
                areg[u] = *(const float4*)(Arow + k0n + t_k + u * 16);
            #pragma unroll
            for (int u = 0; u < 4; u++) {
                const int c4 = b_q + u * 4;
                cpa16(&Bs[(buf ^ 1) * BSTG + b_row * PADB + c4 * 4],
                      Brow + k0n * DIM + c4 * 4);
            }
            asm volatile("cp.async.commit_group;");
        }

        const u64*   aB = AsD + buf * ASTG + ty * 4;
        const float* bB = Bs + buf * BSTG + tx * 4;

        #pragma unroll 8
        for (int k = 0; k < PBK; k++) {
            ulonglong2 b = *(const ulonglong2*)(bB + k * PADB);
            u64 a0 = aB[k * PADA + 0];
            u64 a1 = aB[k * PADA + 1];
            u64 a2 = aB[k * PADA + 2];
            u64 a3 = aB[k * PADA + 3];
            acc[0][0] = fma2(a0, b.x, acc[0][0]); acc[0][1] = fma2(a0, b.y, acc[0][1]);
            acc[1][0] = fma2(a1, b.x, acc[1][0]); acc[1][1] = fma2(a1, b.y, acc[1][1]);
            acc[2][0] = fma2(a2, b.x, acc[2][0]); acc[2][1] = fma2(a2, b.y, acc[2][1]);
            acc[3][0] = fma2(a3, b.x, acc[3][0]); acc[3][1] = fma2(a3, b.y, acc[3][1]);
        }

        if (s < 3) {
            u64* dst = AsD + (buf ^ 1) * ASTG;
            #pragma unroll
            for (int u = 0; u < 4; u++) {
                const int kk = t_k + u * 16;
                dst[(kk + 0) * PADA + t_m] = dup2(areg[u].x);
                dst[(kk + 1) * PADA + t_m] = dup2(areg[u].y);
                dst[(kk + 2) * PADA + t_m] = dup2(areg[u].z);
                dst[(kk + 3) * PADA + t_m] = dup2(areg[u].w);
            }
        }
    }

    #pragma unroll
    for (int i = 0; i < 4; i++) {
        const int m = m0 + ty * 4 + i;
        float v[4] = { lo2(acc[i][0]), hi2(acc[i][0]), lo2(acc[i][1]), hi2(acc[i][1]) };
        #pragma unroll
        for (int j = 0; j < 4; j++) {
            const int n = n0 + tx * 4 + j;
            if (is_sup) g_sproj[m * DIM + n] = v[j] + __ldg(b1 + n);
            else        g_qproj[m * DIM + n] = v[j];
        }
    }
}

// ---------------------------------------------------------------------------
// Kernel B: 1024 threads = 32 warps, warp = 8-dim d-team, 16 q in 2 halves.
// Ts fused; atomic-free reduce via pbuf; 8 warps/SMSP for latency hiding.
//   score'[q,s] = 0.5*(Ts[s] + sum_d |qp+sp| * W2[d])
// ---------------------------------------------------------------------------
#define QB 16
#define TPB 1024
#define NWARPS 32
#define SPAD 260
#define CHUNKF 8320
#define ABSMASK 0x7FFFFFFF7FFFFFFFull

__device__ __forceinline__ void prefetch_chunk(float* buf, int c, int tid) {
    #pragma unroll
    for (int i = 0; i < 2; i++) {
        int f   = tid + i * TPB;    // 0..2047
        int row = f >> 6;
        int c4  = f & 63;
        cpa16(buf + row * SPAD + c4 * 4, g_sproj + (c * 32 + row) * DIM + c4 * 4);
    }
    asm volatile("cp.async.commit_group;");
}

__global__ void __launch_bounds__(TPB, 1) score_kernel(
    const int* __restrict__ labels, const float* __restrict__ W2,
    float* __restrict__ out)
{
    extern __shared__ float sm[];
    float* sp    = sm;                         // 2 * 8320
    float* qp    = sm + 2 * CHUNKF;            // 16*256 = 4096
    float* w2s   = qp + QB * DIM;              // 256
    float* pbuf  = w2s + DIM;                  // 32*16*32 = 16384
    float* tbuf  = pbuf + NWARPS * QB * 32;    // 32*32 = 1024
    float* part  = tbuf + NWARPS * 32;         // 16*320 = 5120
    float* tpart = part + QB * NS;             // 320
    float* sacc  = tpart + NS;                 // 320
    int*   lbl   = (int*)(sacc + QB * NWAY);   // 320

    const int tid  = threadIdx.x;
    const int warp = tid >> 5;                 // d-team, 8 dims each
    const int lane = tid & 31;                 // s within chunk
    const int qbase = blockIdx.x * QB;

    prefetch_chunk(sp, 0, tid);

    {
        const float4* qsrc = (const float4*)(g_qproj + qbase * DIM);
        ((float4*)qp)[tid] = qsrc[tid];        // exactly 1024 float4
        if (tid < DIM / 4) ((float4*)w2s)[tid] = ((const float4*)W2)[tid];
        if (tid < NS) lbl[tid] = labels[tid];
        if (tid < QB * NWAY) sacc[tid] = 0.f;
    }

    const int doff = warp * 8;                 // this team's d-slice (8 dims)

    for (int c = 0; c < 10; c++) {
        asm volatile("cp.async.wait_group 0;");
        __syncthreads();                        // chunk ready; pbuf/tbuf free
        float* cur = sp + (c & 1) * CHUNKF;
        if (c + 1 < 10) prefetch_chunk(sp + ((c + 1) & 1) * CHUNKF, c + 1, tid);

        const ulonglong2* srow = (const ulonglong2*)(cur + lane * SPAD + doff);
        const ulonglong2* w2p  = (const ulonglong2*)(w2s + doff);
        float* pw = pbuf + (warp * QB) * 32;

        #pragma unroll
        for (int h = 0; h < 2; h++) {           // q-halves of 8
            u64 ax[8], ay[8];
            #pragma unroll
            for (int qq = 0; qq < 8; qq++) { ax[qq] = 0ull; ay[qq] = 0ull; }
            u64 t0 = 0ull;

            #pragma unroll
            for (int j = 0; j < 2; j++) {       // 8 dims = 2 ulonglong2
                ulonglong2 sv = srow[j];
                ulonglong2 wv = w2p[j];
                if (h == 0) {                   // fused Ts
                    t0 = fma2(sv.x, wv.x, t0);
                    t0 = fma2(sv.y, wv.y, t0);
                }
                #pragma unroll
                for (int qq = 0; qq < 8; qq++) {
                    const int q = h * 8 + qq;
                    ulonglong2 qv = *(const ulonglong2*)(qp + q * DIM + doff + j * 4);
                    u64 t;
                    t = add2(qv.x, sv.x) & ABSMASK; ax[qq] = fma2(t, wv.x, ax[qq]);
                    t = add2(qv.y, sv.y) & ABSMASK; ay[qq] = fma2(t, wv.y, ay[qq]);
                }
            }

            #pragma unroll
            for (int qq = 0; qq < 8; qq++)
                pw[(h * 8 + qq) * 32 + lane] =
                    (lo2(ax[qq]) + hi2(ax[qq])) + (lo2(ay[qq]) + hi2(ay[qq]));
            if (h == 0)
                tbuf[warp * 32 + lane] = lo2(t0) + hi2(t0);
        }

        __syncthreads();

        // reduce: warps 0..15 -> part (q = warp); warp 16 -> tpart
        if (warp < QB) {
            const int q = warp, sl = lane;
            float s = 0.f;
            #pragma unroll
            for (int w = 0; w < NWARPS; w++)
                s += pbuf[(w * QB + q) * 32 + sl];
            part[q * NS + c * 32 + sl] = s;
        } else if (warp == 16) {
            float s = 0.f;
            #pragma unroll
            for (int w = 0; w < NWARPS; w++)
                s += tbuf[w * 32 + lane];
            tpart[c * 32 + lane] = s;
        }
        // next top-of-loop __syncthreads separates reduce from next writes
    }
    __syncthreads();

    // ---- softmax: warp w (<16) owns q = w ----
    if (warp < QB) {
        const int q = warp;
        float v[10];
        #pragma unroll
        for (int c = 0; c < 10; c++)
            v[c] = 0.5f * (tpart[c * 32 + lane] + part[q * NS + c * 32 + lane]);

        float m = v[0];
        #pragma unroll
        for (int c = 1; c < 10; c++) m = fmaxf(m, v[c]);
        #pragma unroll
        for (int o = 16; o > 0; o >>= 1)
            m = fmaxf(m, __shfl_xor_sync(0xffffffffu, m, o));

        float l = 0.f;
        #pragma unroll
        for (int c = 0; c < 10; c++) {
            float ev = __expf(v[c] - m);
            l += ev;
            atomicAdd(&sacc[q * NWAY + lbl[c * 32 + lane]], ev);
        }
        #pragma unroll
        for (int o = 16; o > 0; o >>= 1)
            l += __shfl_xor_sync(0xffffffffu, l, o);
        const float inv = 1.f / l;
        __syncwarp();

        if (lane < NWAY)
            out[(qbase + q) * NWAY + lane] = sacc[q * NWAY + lane] * inv;
    }
}

// ---------------------------------------------------------------------------
extern "C" void kernel_launch(void* const* d_in, const int* in_sizes, int n_in,
                              void* d_out, int out_size)
{
    (void)in_sizes; (void)n_in; (void)out_size;
    const float* support = (const float*)d_in[0];
    const float* query   = (const float*)d_in[1];
    const int*   labels  = (const int*)d_in[2];
    const float* W1      = (const float*)d_in[3];
    const float* b1      = (const float*)d_in[4];
    const float* W2      = (const float*)d_in[5];
    float* out = (float*)d_out;

    const int proj_smem = (2 * ASTG) * 8 + (2 * BSTG) * 4;  // 101376 B
    cudaFuncSetAttribute(proj_kernel,
                         cudaFuncAttributeMaxDynamicSharedMemorySize, proj_smem);
    proj_kernel<<<dim3(4, 37), 256, proj_smem>>>(support, query, W1, b1);

    const int smem_bytes =
        (2 * CHUNKF + QB * DIM + DIM + NWARPS * QB * 32 + NWARPS * 32
         + QB * NS + NS + QB * NWAY) * 4 + NS * 4;   // 177920 B
    cudaFuncSetAttribute(score_kernel,
                         cudaFuncAttributeMaxDynamicSharedMemorySize, smem_bytes);
    score_kernel<<<NQ / QB, TPB, smem_bytes>>>(labels, W2, out);
}